// round 11
// baseline (speedup 1.0000x reference)
#include <cuda_runtime.h>
#include <math.h>

// ---------------- scratch (no runtime allocation allowed) ----------------
__device__ float g_delta[4 * 64 * 1024];    // (B, D, H*W)
__device__ float g_BC[4 * 16 * 1024 * 2];   // (B, N, H*W, {B,C}) interleaved
__device__ float g_Aneg[64 * 16];           // -exp(log_A_real)
__device__ float g_part[16 * 32 * 2];       // groupnorm partial sums

// rotation constants: c = cos(radians(-w)), s = sin(radians(-w)).
#define RS 0.7071067811865476
__constant__ double d_CS[8] = { 1.0,  RS, 0.0, -RS, -1.0, -RS, 0.0,  RS };
__constant__ double d_SN[8] = { 0.0, -RS, -1.0, -RS,  0.0,  RS, 1.0,  RS };

// padded smem row stride: 37 mod 32 = 5 -> transpose (stride 5, coprime) and
// diagonals (stride 0.707*(1 +/- 5)) all <=2-way bank conflicts.
#define SSTR 37
#define PLANE (SSTR * 32)

// ---------------- kernel 1: groupnorm partial sums + A precompute ----------
// grid = 512 = bg*32 + e, block = 128; one float4 per thread.
__global__ __launch_bounds__(128) void k_gn1(const float* __restrict__ u,
                                             const float* __restrict__ logA) {
    int bg = blockIdx.x >> 5, e = blockIdx.x & 31;
    if (blockIdx.x == 0) {
        #pragma unroll
        for (int i = threadIdx.x; i < 1024; i += 128)
            g_Aneg[i] = -expf(logA[i]);
    }
    const float4* base = (const float4*)(u + (size_t)bg * 16384) + e * 128;
    float4 v4 = __ldg(base + threadIdx.x);
    float s = v4.x + v4.y + v4.z + v4.w;
    float q = v4.x * v4.x + v4.y * v4.y + v4.z * v4.z + v4.w * v4.w;
    #pragma unroll
    for (int o = 16; o; o >>= 1) {
        s += __shfl_down_sync(0xffffffffu, s, o);
        q += __shfl_down_sync(0xffffffffu, q, o);
    }
    __shared__ float shs[4], shq[4];
    int wid = threadIdx.x >> 5, lid = threadIdx.x & 31;
    if (lid == 0) { shs[wid] = s; shq[wid] = q; }
    __syncthreads();
    if (threadIdx.x == 0) {
        float ts = shs[0] + shs[1] + shs[2] + shs[3];
        float tq = shq[0] + shq[1] + shq[2] + shq[3];
        g_part[(bg * 32 + e) * 2 + 0] = ts;
        g_part[(bg * 32 + e) * 2 + 1] = tq;
    }
}

// ---------------- kernel 2: fused groupnorm + 3x3 convs (delta / B / C) ----
// grid = 4b * 48 ocpairs * 4 quarters = 768 blocks, block = 128 (4 warps).
__global__ __launch_bounds__(128) void k_conv(const float* __restrict__ u,
                                              const float* __restrict__ gw,
                                              const float* __restrict__ gb,
                                              const float* __restrict__ wd,
                                              const float* __restrict__ bdelta,
                                              const float* __restrict__ wB,
                                              const float* __restrict__ wC,
                                              const float* __restrict__ dtb) {
    int bx = blockIdx.x;
    int b = bx / 192;
    int rem = bx % 192;
    int ocg = rem >> 2;
    int quarter = rem & 3;
    int warp = threadIdx.x >> 5;
    int x = threadIdx.x & 31;
    int rbase = quarter * 8 + warp * 2;
    int oc0 = ocg * 2;

    const float* wbase;
    if (oc0 < 64)       wbase = wd + (size_t)oc0 * 576;
    else if (oc0 < 80)  wbase = wB + (size_t)(oc0 - 64) * 576;
    else                wbase = wC + (size_t)(oc0 - 80) * 576;

    __shared__ float swt[1152];
    __shared__ float ssc[64], ssh[64];
    for (int i = threadIdx.x; i < 1152; i += 128) swt[i] = __ldg(wbase + i);
    if (threadIdx.x < 64) {
        int ch = threadIdx.x;
        int g = ch >> 4;
        float ts = 0.f, tq = 0.f;
        #pragma unroll
        for (int k = 0; k < 32; ++k) {
            ts += g_part[((b * 4 + g) * 32 + k) * 2 + 0];
            tq += g_part[((b * 4 + g) * 32 + k) * 2 + 1];
        }
        float mu = ts * (1.f / 16384.f);
        float var = tq * (1.f / 16384.f) - mu * mu;
        float rs = rsqrtf(var + 1e-5f);
        float sc = rs * __ldg(gw + ch);
        ssc[ch] = sc;
        ssh[ch] = __ldg(gb + ch) - mu * sc;
    }
    __syncthreads();

    const float* inb = u + (size_t)b * 65536;

    float acc0[2] = {0.f, 0.f};
    float acc1[2] = {0.f, 0.f};

    for (int din = 0; din < 64; ++din) {
        const float* ip = inb + din * 1024;
        float sc = ssc[din], sh = ssh[din];
        float cc[4], ll[4], rr[4];
        #pragma unroll
        for (int j = 0; j < 4; ++j) {
            int ry = rbase - 1 + j;
            cc[j] = ((unsigned)ry < 32u)
                  ? fmaf(__ldg(ip + ry * 32 + x), sc, sh) : 0.f;
        }
        #pragma unroll
        for (int j = 0; j < 4; ++j) {
            float uu = __shfl_up_sync(0xffffffffu, cc[j], 1);
            float dd = __shfl_down_sync(0xffffffffu, cc[j], 1);
            ll[j] = (x == 0) ? 0.f : uu;
            rr[j] = (x == 31) ? 0.f : dd;
        }
        const float* wp0 = swt + din * 9;
        const float* wp1 = wp0 + 576;
        #pragma unroll
        for (int r = 0; r < 2; ++r) {
            #pragma unroll
            for (int ky = 0; ky < 3; ++ky) {
                int j = r + ky;
                acc0[r] = fmaf(ll[j], wp0[ky * 3 + 0], acc0[r]);
                acc0[r] = fmaf(cc[j], wp0[ky * 3 + 1], acc0[r]);
                acc0[r] = fmaf(rr[j], wp0[ky * 3 + 2], acc0[r]);
                acc1[r] = fmaf(ll[j], wp1[ky * 3 + 0], acc1[r]);
                acc1[r] = fmaf(cc[j], wp1[ky * 3 + 1], acc1[r]);
                acc1[r] = fmaf(rr[j], wp1[ky * 3 + 2], acc1[r]);
            }
        }
    }

    float dt = __ldg(dtb);
    #pragma unroll
    for (int which = 0; which < 2; ++which) {
        int oc = oc0 + which;
        #pragma unroll
        for (int r = 0; r < 2; ++r) {
            int p = (rbase + r) * 32 + x;
            float a = which ? acc1[r] : acc0[r];
            if (oc < 64) {
                float v = a + __ldg(bdelta + oc) + dt;
                float sp = (v > 0.f) ? v + log1pf(__expf(-v)) : log1pf(__expf(v));
                g_delta[((size_t)b * 64 + oc) * 1024 + p] = fminf(fmaxf(sp, 1e-4f), 5.f);
            } else if (oc < 80) {
                g_BC[(((size_t)b * 16 + (oc - 64)) * 1024 + p) * 2 + 0] = a;
            } else {
                g_BC[(((size_t)b * 16 + (oc - 80)) * 1024 + p) * 2 + 1] = a;
            }
        }
    }
}

// ---------------- kernel 3: transport + SSM update + einsum ----------------
// grid = 2048 = (b*8+v)*64+d, block = 1024 (one pixel each), 2 blocks/SM.
// v in {0,180}: direct streaming (no smem). Other v: cp.async stages 16
// planes in 4 commit groups (finer pipeline), then gathers from padded smem.
// All streaming traffic uses evict-first (.cs) hints so g_BC/g_delta stay
// L2-resident under the 276 MB s_prev/s_new stream.
__global__ __launch_bounds__(1024, 2) void k_trans(const float* __restrict__ u_t,
                                                   const float* __restrict__ s_prev,
                                                   const float* __restrict__ Dp,
                                                   float* __restrict__ out) {
    extern __shared__ float sbuf[];   // [16][PLANE]

    int bx = blockIdx.x;
    int d = bx & 63;
    int v = (bx >> 6) & 7;
    int b = bx >> 9;
    int p = threadIdx.x;
    int h = p >> 5;
    int w = p & 31;

    size_t sb = (((size_t)(b * 8 + v) * 64 + d) * 16) * 1024;
    const float* sp = s_prev + sb;
    float* so = out + 2097152 + sb;              // s_new after y_new block

    size_t bd = ((size_t)b * 64 + d) * 1024 + p;
    float delta = __ldcs(g_delta + bd);
    float u = __ldcs(u_t + bd);
    float du = delta * u;
    const float* anp = g_Aneg + d * 16;
    const float2* bcp = (const float2*)g_BC + (size_t)b * 16384 + p;
    float y = 0.f;

    if ((v & 3) == 0) {
        // v==0 (identity) or v==4 (180deg: index reversal) — direct path
        int rp = v ? (1023 - p) : p;
        #pragma unroll
        for (int n = 0; n < 16; ++n) {
            float st = __ldcs(sp + n * 1024 + rp);
            float2 bc = __ldg(bcp + n * 1024);
            float abar = __expf(delta * __ldg(anp + n));
            float snew = fmaf(abar, st, du * bc.x);
            __stcs(so + n * 1024 + p, snew);
            y = fmaf(snew, bc.y, y);
        }
    } else {
        int srow = h * SSTR + w;
        unsigned sa = (unsigned)__cvta_generic_to_shared(sbuf + srow);

        // stage all 16 planes in 4 commit groups of 4
        #pragma unroll
        for (int gq = 0; gq < 4; ++gq) {
            #pragma unroll
            for (int k = 0; k < 4; ++k) {
                int n = gq * 4 + k;
                asm volatile("cp.async.ca.shared.global [%0], [%1], 4;" ::
                             "r"(sa + n * (PLANE * 4)), "l"(sp + n * 1024 + p));
            }
            asm volatile("cp.async.commit_group;");
        }

        // sampling coords in double, matching the reference's float64 grid
        double c = d_CS[v], s = d_SN[v];
        double xs = ((double)w + 0.5) * 0.0625 - 1.0;
        double ys = ((double)h + 0.5) * 0.0625 - 1.0;
        float ix = (float)((c * xs - s * ys + 1.0) * 16.0 - 0.5);
        float iy = (float)((s * xs + c * ys + 1.0) * 16.0 - 0.5);

        float x0 = floorf(ix), y0 = floorf(iy);
        float fx1 = ix - x0, fy1 = iy - y0;
        float fx0 = 1.f - fx1, fy0 = 1.f - fy1;
        int xi0 = (int)x0, yi0 = (int)y0;

        bool cardinal = ((v & 1) == 0);   // 90/270: exact integer permutation

        int soff[4];
        float wt[4];
        #pragma unroll
        for (int c4 = 0; c4 < 4; ++c4) {
            int dy = c4 >> 1, dx = c4 & 1;
            int yc = yi0 + dy, xc = xi0 + dx;
            bool m = ((unsigned)yc < 32u) && ((unsigned)xc < 32u);
            int yi = min(max(yc, 0), 31);
            int xi = min(max(xc, 0), 31);
            soff[c4] = yi * SSTR + xi;
            float ww = (dy ? fy1 : fy0) * (dx ? fx1 : fx0);
            wt[c4] = m ? ww : 0.f;
        }

        #pragma unroll
        for (int gq = 0; gq < 4; ++gq) {
            if (gq == 0)      asm volatile("cp.async.wait_group 3;");
            else if (gq == 1) asm volatile("cp.async.wait_group 2;");
            else if (gq == 2) asm volatile("cp.async.wait_group 1;");
            else              asm volatile("cp.async.wait_group 0;");
            __syncthreads();
            #pragma unroll
            for (int k = 0; k < 4; ++k) {
                int n = gq * 4 + k;
                const float* pl = sbuf + n * PLANE;
                float st = cardinal ? pl[soff[0]]
                                    : wt[0] * pl[soff[0]] + wt[1] * pl[soff[1]] +
                                      wt[2] * pl[soff[2]] + wt[3] * pl[soff[3]];
                float2 bc = __ldg(bcp + n * 1024);
                float abar = __expf(delta * __ldg(anp + n));
                float snew = fmaf(abar, st, du * bc.x);
                __stcs(so + n * 1024 + p, snew);
                y = fmaf(snew, bc.y, y);
            }
        }
    }
    __stcs(out + ((size_t)(b * 8 + v) * 64 + d) * 1024 + p, y + u * __ldg(Dp + d));
}

// ---------------- launch ----------------
extern "C" void kernel_launch(void* const* d_in, const int* in_sizes, int n_in,
                              void* d_out, int out_size) {
    const float* u_t     = (const float*)d_in[0];
    const float* s_prev  = (const float*)d_in[1];
    const float* gn_w    = (const float*)d_in[2];
    const float* gn_b    = (const float*)d_in[3];
    const float* cdw     = (const float*)d_in[4];
    const float* cdb     = (const float*)d_in[5];
    const float* cBw     = (const float*)d_in[6];
    const float* cCw     = (const float*)d_in[7];
    const float* logA    = (const float*)d_in[8];
    const float* Dp      = (const float*)d_in[9];
    const float* dtb     = (const float*)d_in[10];
    float* out = (float*)d_out;                     // y_new ++ s_new

    cudaFuncSetAttribute(k_trans, cudaFuncAttributeMaxDynamicSharedMemorySize,
                         16 * PLANE * 4);

    k_gn1<<<512, 128>>>(u_t, logA);
    k_conv<<<768, 128>>>(u_t, gn_w, gn_b, cdw, cdb, cBw, cCw, dtb);
    k_trans<<<2048, 1024, 16 * PLANE * 4>>>(u_t, s_prev, Dp, out);
}